// round 4
// baseline (speedup 1.0000x reference)
#include <cuda_runtime.h>
#include <cuda_bf16.h>
#include <cstdint>

#define NEGC 1000000000000.0f
#define B_ 8
#define L_ 512
#define H_ 768
#define O_ 12
#define NN_ (O_*H_)   // 9216
#define ML_ (B_*L_)   // 4096

#define BM 128
#define BN 128
#define BKB 128        // k-bytes (= fp8 elements) per chunk: one SW128 row
#define NC (H_/BKB)    // 6
#define STG_BYTES 32768u

// Scratch (__device__ globals per allocation rules)
__device__ uint8_t g_X8 [(size_t)ML_*H_];
__device__ uint8_t g_W1t8[(size_t)NN_*H_];
__device__ uint8_t g_T8 [(size_t)ML_*NN_];   // 37.7 MB fp8
__device__ float g_lini[ML_*O_];
__device__ float g_linj[ML_*O_];

__device__ __forceinline__ uint32_t swz(uint32_t off){ return off ^ ((off>>3)&0x70); }
__device__ __forceinline__ void cp16(uint32_t saddr, const void* g){
    asm volatile("cp.async.cg.shared.global [%0], [%1], 16;\n" :: "r"(saddr), "l"(g));
}
// pack 2 floats -> e4m3x2 (lo = first arg)
__device__ __forceinline__ uint16_t pk8(float lo, float hi){
    uint16_t r;
    asm("cvt.rn.satfinite.e4m3x2.f32 %0, %2, %1;" : "=h"(r) : "f"(lo), "f"(hi));
    return r;
}

#define LDM4(d0,d1,d2,d3,addr) \
  asm volatile("ldmatrix.sync.aligned.m8n8.x4.shared.b16 {%0,%1,%2,%3}, [%4];\n" \
    : "=r"(d0),"=r"(d1),"=r"(d2),"=r"(d3) : "r"(addr))

#define MMAFP8(c,a0,a1,a2,a3,b0,b1) \
  asm volatile("mma.sync.aligned.m16n8k32.row.col.f32.e4m3.e4m3.f32 " \
    "{%0,%1,%2,%3}, {%4,%5,%6,%7}, {%8,%9}, {%0,%1,%2,%3};\n" \
    : "+f"(c[0]),"+f"(c[1]),"+f"(c[2]),"+f"(c[3]) \
    : "r"(a0),"r"(a1),"r"(a2),"r"(a3),"r"(b0),"r"(b1))

// ---------------------------------------------------------------------------
__global__ void conv_x(const float* __restrict__ X){
    int i = blockIdx.x*256 + threadIdx.x;          // 4 floats -> 4 fp8
    float4 v = ((const float4*)X)[i];
    uint32_t pk = (uint32_t)pk8(v.x, v.y) | ((uint32_t)pk8(v.z, v.w) << 16);
    ((uint32_t*)g_X8)[i] = pk;
}

// W1[i][o*H+j] fp32 -> W1t8[o*H+j][i] fp8 (tiled transpose)
__global__ void conv_w1(const float* __restrict__ W1){
    __shared__ float t[32][33];
    int n0 = blockIdx.x*32, i0 = blockIdx.y*32;
    int tx = threadIdx.x, ty = threadIdx.y;        // (32, 8)
#pragma unroll
    for (int r = 0; r < 4; r++)
        t[ty+8*r][tx] = W1[(size_t)(i0+ty+8*r)*NN_ + n0+tx];
    __syncthreads();
    int id = ty*32 + tx;
    int nl = id >> 3, il0 = (id & 7)*4;
    uint32_t pk = (uint32_t)pk8(t[il0][nl],   t[il0+1][nl])
                | ((uint32_t)pk8(t[il0+2][nl], t[il0+3][nl]) << 16);
    *(uint32_t*)&g_W1t8[(size_t)(n0+nl)*H_ + i0 + il0] = pk;
}

__global__ void lin_kernel(const float* __restrict__ X, const float* __restrict__ W2){
    int warp = (blockIdx.x*blockDim.x + threadIdx.x) >> 5;
    int lane = threadIdx.x & 31;
    if (warp >= ML_) return;
    const float* xr = X + (size_t)warp*H_;
    float si[O_] = {}, sj[O_] = {};
    for (int k = lane; k < H_; k += 32){
        float xv = xr[k];
        const float* wa = W2 + k*O_;
        const float* wb = W2 + (H_+k)*O_;
#pragma unroll
        for (int o = 0; o < O_; o++){
            si[o] = fmaf(xv, wa[o], si[o]);
            sj[o] = fmaf(xv, wb[o], sj[o]);
        }
    }
#pragma unroll
    for (int o = 0; o < O_; o++){
#pragma unroll
        for (int off = 16; off; off >>= 1){
            si[o] += __shfl_xor_sync(0xFFFFFFFFu, si[o], off);
            sj[o] += __shfl_xor_sync(0xFFFFFFFFu, sj[o], off);
        }
    }
    if (lane == 0){
#pragma unroll
        for (int o = 0; o < O_; o++){
            g_lini[warp*O_ + o] = si[o];
            g_linj[warp*O_ + o] = sj[o];
        }
    }
}

// ---------------------------------------------------------------------------
__device__ __forceinline__ void fill_tiles(uint32_t sb, int stg,
    const uint8_t* Agl, const uint8_t* Bgl, size_t lda, size_t ldb,
    int kt, int lr, int lc)
{
    uint32_t ab = sb + stg*STG_BYTES, bb = ab + 16384u;
#pragma unroll
    for (int q = 0; q < 4; q++)
        cp16(ab + swz((lr+32*q)*128 + lc*16), Agl + (size_t)(32*q)*lda + kt);
#pragma unroll
    for (int q = 0; q < 4; q++)
        cp16(bb + swz((lr+32*q)*128 + lc*16), Bgl + (size_t)(32*q)*ldb + kt);
    asm volatile("cp.async.commit_group;\n");
}

// STAGE 1: T8[(b x)][(o j)] = X8 @ W1t8^T   (M=4096, N=9216, K=768)
// STAGE 2: per (b,o): C[x][y] = T8-slice @ X8-slice^T + fused epilogue -> out
template<int STAGE>
__global__ __launch_bounds__(256, 2) void fp8_gemm(
    const float* __restrict__ W2, const int* __restrict__ mask, float* __restrict__ out)
{
    extern __shared__ __align__(1024) char smem[];
    uint32_t sb = (uint32_t)__cvta_generic_to_shared(smem);
    int tid = threadIdx.x, lane = tid & 31, warp = tid >> 5;
    int wm = warp >> 1, wn = warp & 1;             // 4x2 warps, 32x64 each

    int bm, bn, b = 0, o = 0, bo = 0;
    const uint8_t *Ag, *Bg;
    size_t lda, ldb;
    if (STAGE == 1){
        bm = blockIdx.y*BM; bn = blockIdx.x*BN;
        Ag = g_X8   + (size_t)bm*H_; lda = H_;
        Bg = g_W1t8 + (size_t)bn*H_; ldb = H_;
    } else {
        bo = blockIdx.z; b = bo / O_; o = bo % O_;
        bm = blockIdx.y*BM; bn = blockIdx.x*BN;
        Ag = g_T8 + (size_t)(b*L_+bm)*NN_ + o*H_; lda = NN_;
        Bg = g_X8 + (size_t)(b*L_+bn)*H_;         ldb = H_;
    }

    // Causal tile skip: whole tile has y < x -> output depends on masks only.
    if (STAGE == 2 && bn + BN <= bm){
        int r0 = tid >> 1;
        int cb = (tid & 1)*64;
        int x  = bm + r0;
        int mx = mask[b*L_ + x];
        const int* mrow = mask + b*L_ + bn + cb;
        float* orow = out + (size_t)bo*L_*L_ + (size_t)x*L_ + bn + cb;
#pragma unroll
        for (int j = 0; j < 64; j += 4){
            float4 v;
            v.x = (mx && mrow[j+0]) ? -NEGC : (-NEGC - NEGC);
            v.y = (mx && mrow[j+1]) ? -NEGC : (-NEGC - NEGC);
            v.z = (mx && mrow[j+2]) ? -NEGC : (-NEGC - NEGC);
            v.w = (mx && mrow[j+3]) ? -NEGC : (-NEGC - NEGC);
            *(float4*)&orow[j] = v;
        }
        return;
    }

    int lr = tid >> 3, lc = tid & 7;               // loader: 32 rows x 8 chunks of 16B
    const uint8_t* Agl = Ag + (size_t)lr*lda + lc*16;
    const uint8_t* Bgl = Bg + (size_t)lr*ldb + lc*16;

    float acc[2][8][4];
#pragma unroll
    for (int i=0;i<2;i++) for (int j=0;j<8;j++) for (int k=0;k<4;k++) acc[i][j][k]=0.f;

    // 3-stage prologue
    fill_tiles(sb, 0, Agl, Bgl, lda, ldb, 0,   lr, lc);
    fill_tiles(sb, 1, Agl, Bgl, lda, ldb, BKB, lr, lc);

    int rsel = lane & 15, hi = lane >> 4;
    for (int c = 0; c < NC; c++){
        if (c + 1 < NC) asm volatile("cp.async.wait_group 1;\n");
        else            asm volatile("cp.async.wait_group 0;\n");
        __syncthreads();

        uint32_t ab = sb + (uint32_t)(c % 3)*STG_BYTES, bb = ab + 16384u;
#pragma unroll
        for (int ks = 0; ks < 4; ks++){            // 4 x k32 slices = 128 k-bytes
            uint32_t a[2][4], bf[4][4];
#pragma unroll
            for (int mt = 0; mt < 2; mt++){
                uint32_t off = (wm*32 + mt*16 + rsel)*128 + ks*32 + hi*16;
                LDM4(a[mt][0],a[mt][1],a[mt][2],a[mt][3], ab + swz(off));
            }
#pragma unroll
            for (int p = 0; p < 4; p++){
                uint32_t off = (wn*64 + p*16 + rsel)*128 + ks*32 + hi*16;
                LDM4(bf[p][0],bf[p][1],bf[p][2],bf[p][3], bb + swz(off));
            }
#pragma unroll
            for (int mt = 0; mt < 2; mt++)
#pragma unroll
                for (int nt = 0; nt < 8; nt++)
                    MMAFP8(acc[mt][nt], a[mt][0],a[mt][1],a[mt][2],a[mt][3],
                           bf[nt>>1][nt&1], bf[nt>>1][2+(nt&1)]);
        }
        if (c + 2 < NC)
            fill_tiles(sb, (c + 2) % 3, Agl, Bgl, lda, ldb, (c+2)*BKB, lr, lc);
    }

    int g = lane >> 2, t2 = (lane & 3)*2;
    if (STAGE == 1){
#pragma unroll
        for (int mt = 0; mt < 2; mt++){
            int row = bm + wm*32 + mt*16 + g;
#pragma unroll
            for (int nt = 0; nt < 8; nt++){
                int col = bn + wn*64 + nt*8 + t2;
                *(uint16_t*)&g_T8[(size_t)row*NN_ + col] =
                    pk8(acc[mt][nt][0], acc[mt][nt][1]);
                *(uint16_t*)&g_T8[(size_t)(row+8)*NN_ + col] =
                    pk8(acc[mt][nt][2], acc[mt][nt][3]);
            }
        }
    } else {
        float bias = W2[2*H_*O_ + o];
        int myv[16]; float lj[16];
#pragma unroll
        for (int nt = 0; nt < 8; nt++){
            int y = bn + wn*64 + nt*8 + t2;
            myv[2*nt]   = mask[b*L_+y];
            myv[2*nt+1] = mask[b*L_+y+1];
            lj[2*nt]    = g_linj[(b*L_+y)*O_+o];
            lj[2*nt+1]  = g_linj[(b*L_+y+1)*O_+o];
        }
#pragma unroll
        for (int mt = 0; mt < 2; mt++)
#pragma unroll
            for (int half = 0; half < 2; half++){
                int x  = bm + wm*32 + mt*16 + g + half*8;
                int mx = mask[b*L_+x];
                float li = g_lini[(b*L_+x)*O_+o] + bias;
                float* orow = out + (size_t)bo*L_*L_ + (size_t)x*L_;
#pragma unroll
                for (int nt = 0; nt < 8; nt++){
                    int y = bn + wn*64 + nt*8 + t2;
                    float v0 = acc[mt][nt][half*2+0] + li + lj[2*nt];
                    float v1 = acc[mt][nt][half*2+1] + li + lj[2*nt+1];
                    if (!mx)         { v0 = -NEGC; v1 = -NEGC; }
                    if (!myv[2*nt])    v0 = -NEGC;
                    if (!myv[2*nt+1])  v1 = -NEGC;
                    if (y   < x)       v0 -= NEGC;
                    if (y+1 < x)       v1 -= NEGC;
                    *(float2*)&orow[y] = make_float2(v0, v1);
                }
            }
    }
}

// ---------------------------------------------------------------------------
extern "C" void kernel_launch(void* const* d_in, const int* in_sizes, int n_in,
                              void* d_out, int out_size) {
    const float* inputs = nullptr;
    const float* w1 = nullptr;
    const float* w2 = nullptr;
    const int*   mask = nullptr;
    for (int i = 0; i < n_in; i++) {
        if      (in_sizes[i] == B_*L_*H_)      inputs = (const float*)d_in[i];
        else if (in_sizes[i] == H_*O_*H_)      w1     = (const float*)d_in[i];
        else if (in_sizes[i] == (2*H_+1)*O_)   w2     = (const float*)d_in[i];
        else if (in_sizes[i] == B_*L_)         mask   = (const int*)d_in[i];
    }
    float* out = (float*)d_out;

    cudaFuncSetAttribute(fp8_gemm<1>, cudaFuncAttributeMaxDynamicSharedMemorySize, 3*STG_BYTES);
    cudaFuncSetAttribute(fp8_gemm<2>, cudaFuncAttributeMaxDynamicSharedMemorySize, 3*STG_BYTES);

    conv_x<<<(ML_*H_/4)/256, 256>>>(inputs);
    conv_w1<<<dim3(NN_/32, H_/32), dim3(32,8)>>>(w1);
    lin_kernel<<<ML_/8, 256>>>(inputs, w2);
    fp8_gemm<1><<<dim3(NN_/BN, ML_/BM), 256, 3*STG_BYTES>>>(w2, mask, out);
    fp8_gemm<2><<<dim3(L_/BN, L_/BM, B_*O_), 256, 3*STG_BYTES>>>(w2, mask, out);
}

// round 6
// speedup vs baseline: 1.1440x; 1.1440x over previous
#include <cuda_runtime.h>
#include <cuda_bf16.h>
#include <cstdint>

#define NEGC 1000000000000.0f
#define B_ 8
#define L_ 512
#define H_ 768
#define O_ 12
#define NN_ (O_*H_)   // 9216
#define ML_ (B_*L_)   // 4096

#define BM 128
#define BN 128
#define BK 64
#define NC (H_/BK)     // 12
#define STG_BYTES 32768u

// Scratch (__device__ globals per allocation rules)
__device__ __nv_bfloat16 g_Xb[(size_t)ML_*H_];
__device__ __nv_bfloat16 g_W1t[(size_t)NN_*H_];
__device__ __nv_bfloat16 g_Tb[(size_t)ML_*NN_];     // 75.5 MB bf16
__device__ float g_lini[ML_*O_];
__device__ float g_linj[ML_*O_];

__device__ __forceinline__ uint32_t swz(uint32_t off){ return off ^ ((off>>3)&0x70); }
__device__ __forceinline__ void cp16(uint32_t saddr, const void* g){
    asm volatile("cp.async.cg.shared.global [%0], [%1], 16;\n" :: "r"(saddr), "l"(g));
}

#define LDM4(d0,d1,d2,d3,addr) \
  asm volatile("ldmatrix.sync.aligned.m8n8.x4.shared.b16 {%0,%1,%2,%3}, [%4];\n" \
    : "=r"(d0),"=r"(d1),"=r"(d2),"=r"(d3) : "r"(addr))

#define MMA16816(c,a0,a1,a2,a3,b0,b1) \
  asm volatile("mma.sync.aligned.m16n8k16.row.col.f32.bf16.bf16.f32 " \
    "{%0,%1,%2,%3}, {%4,%5,%6,%7}, {%8,%9}, {%0,%1,%2,%3};\n" \
    : "+f"(c[0]),"+f"(c[1]),"+f"(c[2]),"+f"(c[3]) \
    : "r"(a0),"r"(a1),"r"(a2),"r"(a3),"r"(b0),"r"(b1))

// ---------------------------------------------------------------------------
__global__ void conv_x(const float* __restrict__ X){
    int i = blockIdx.x*256 + threadIdx.x;
    float4 v = ((const float4*)X)[i];
    ((__nv_bfloat162*)g_Xb)[2*i]   = __floats2bfloat162_rn(v.x, v.y);
    ((__nv_bfloat162*)g_Xb)[2*i+1] = __floats2bfloat162_rn(v.z, v.w);
}

__global__ void conv_w1(const float* __restrict__ W1){
    __shared__ float t[32][33];
    int n0 = blockIdx.x*32, i0 = blockIdx.y*32;
    int tx = threadIdx.x, ty = threadIdx.y;        // (32, 8)
#pragma unroll
    for (int r = 0; r < 4; r++)
        t[ty+8*r][tx] = W1[(size_t)(i0+ty+8*r)*NN_ + n0+tx];
    __syncthreads();
#pragma unroll
    for (int r = 0; r < 4; r++)
        g_W1t[(size_t)(n0+ty+8*r)*H_ + i0+tx] = __float2bfloat16_rn(t[tx][ty+8*r]);
}

__global__ void lin_kernel(const float* __restrict__ X, const float* __restrict__ W2){
    int warp = (blockIdx.x*blockDim.x + threadIdx.x) >> 5;
    int lane = threadIdx.x & 31;
    if (warp >= ML_) return;
    const float* xr = X + (size_t)warp*H_;
    float si[O_] = {}, sj[O_] = {};
    for (int k = lane; k < H_; k += 32){
        float xv = xr[k];
        const float* wa = W2 + k*O_;
        const float* wb = W2 + (H_+k)*O_;
#pragma unroll
        for (int o = 0; o < O_; o++){
            si[o] = fmaf(xv, wa[o], si[o]);
            sj[o] = fmaf(xv, wb[o], sj[o]);
        }
    }
#pragma unroll
    for (int o = 0; o < O_; o++){
#pragma unroll
        for (int off = 16; off; off >>= 1){
            si[o] += __shfl_xor_sync(0xFFFFFFFFu, si[o], off);
            sj[o] += __shfl_xor_sync(0xFFFFFFFFu, sj[o], off);
        }
    }
    if (lane == 0){
#pragma unroll
        for (int o = 0; o < O_; o++){
            g_lini[warp*O_ + o] = si[o];
            g_linj[warp*O_ + o] = sj[o];
        }
    }
}

// ---------------------------------------------------------------------------
__device__ __forceinline__ void fill_tiles(uint32_t sb, int stg,
    const __nv_bfloat16* Agl, const __nv_bfloat16* Bgl, size_t lda, size_t ldb,
    int kt, int lr, int lc)
{
    uint32_t ab = sb + (uint32_t)stg*STG_BYTES, bb = ab + 16384u;
#pragma unroll
    for (int q = 0; q < 4; q++)
        cp16(ab + swz((lr+32*q)*128 + lc*16), Agl + (size_t)(32*q)*lda + kt);
#pragma unroll
    for (int q = 0; q < 4; q++)
        cp16(bb + swz((lr+32*q)*128 + lc*16), Bgl + (size_t)(32*q)*ldb + kt);
    asm volatile("cp.async.commit_group;\n");
}

// STAGE 1: Tb[(b x)][(o j)] = Xb @ W1t^T   (M=4096, N=9216, K=768)
// STAGE 2: per (b,o): C[x][y] = Tb-slice @ Xb-slice^T + fused epilogue -> out
template<int STAGE>
__global__ __launch_bounds__(256, 2) void mma_gemm(
    const float* __restrict__ W2, const int* __restrict__ mask, float* __restrict__ out)
{
    extern __shared__ __align__(1024) char smem[];
    uint32_t sb = (uint32_t)__cvta_generic_to_shared(smem);
    int tid = threadIdx.x, lane = tid & 31, warp = tid >> 5;
    int wm = warp >> 1, wn = warp & 1;             // 4x2 warps, 32x64 each

    int bm, bn, b = 0, o = 0, bo = 0;
    const __nv_bfloat16 *Ag, *Bg;
    size_t lda, ldb;
    if (STAGE == 1){
        bm = blockIdx.y*BM; bn = blockIdx.x*BN;
        Ag = g_Xb  + (size_t)bm*H_; lda = H_;
        Bg = g_W1t + (size_t)bn*H_; ldb = H_;
    } else {
        bo = blockIdx.z; b = bo / O_; o = bo % O_;
        bm = blockIdx.y*BM; bn = blockIdx.x*BN;
        Ag = g_Tb + (size_t)(b*L_+bm)*NN_ + o*H_; lda = NN_;
        Bg = g_Xb + (size_t)(b*L_+bn)*H_;         ldb = H_;
    }

    // Causal tile skip: whole tile y < x -> masks-only constants, no GEMM.
    if (STAGE == 2 && bn + BN <= bm){
        int r0 = tid >> 1;
        int cb = (tid & 1)*64;
        int x  = bm + r0;
        int mx = mask[b*L_ + x];
        const int* mrow = mask + b*L_ + bn + cb;
        float* orow = out + (size_t)bo*L_*L_ + (size_t)x*L_ + bn + cb;
#pragma unroll
        for (int j = 0; j < 64; j += 4){
            float4 v;
            v.x = (mx && mrow[j+0]) ? -NEGC : (-NEGC - NEGC);
            v.y = (mx && mrow[j+1]) ? -NEGC : (-NEGC - NEGC);
            v.z = (mx && mrow[j+2]) ? -NEGC : (-NEGC - NEGC);
            v.w = (mx && mrow[j+3]) ? -NEGC : (-NEGC - NEGC);
            *(float4*)&orow[j] = v;
        }
        return;
    }

    int lr = tid >> 3, lc = tid & 7;               // loader: 32 rows x 8 chunks of 16B
    const __nv_bfloat16* Agl = Ag + (size_t)lr*lda + lc*8;
    const __nv_bfloat16* Bgl = Bg + (size_t)lr*ldb + lc*8;

    float acc[2][8][4];
#pragma unroll
    for (int i=0;i<2;i++) for (int j=0;j<8;j++) for (int k=0;k<4;k++) acc[i][j][k]=0.f;

    // 3-stage prologue
    fill_tiles(sb, 0, Agl, Bgl, lda, ldb, 0,  lr, lc);
    fill_tiles(sb, 1, Agl, Bgl, lda, ldb, BK, lr, lc);

    int rsel = lane & 15, hi = lane >> 4;
    for (int c = 0; c < NC; c++){
        if (c + 1 < NC) asm volatile("cp.async.wait_group 1;\n");
        else            asm volatile("cp.async.wait_group 0;\n");
        __syncthreads();

        uint32_t ab = sb + (uint32_t)(c % 3)*STG_BYTES, bb = ab + 16384u;
#pragma unroll
        for (int ks = 0; ks < 4; ks++){
            uint32_t a[2][4], bf[4][4];
#pragma unroll
            for (int mt = 0; mt < 2; mt++){
                uint32_t off = (wm*32 + mt*16 + rsel)*128 + ks*32 + hi*16;
                LDM4(a[mt][0],a[mt][1],a[mt][2],a[mt][3], ab + swz(off));
            }
#pragma unroll
            for (int p = 0; p < 4; p++){
                uint32_t off = (wn*64 + p*16 + rsel)*128 + ks*32 + hi*16;
                LDM4(bf[p][0],bf[p][1],bf[p][2],bf[p][3], bb + swz(off));
            }
#pragma unroll
            for (int mt = 0; mt < 2; mt++)
#pragma unroll
                for (int nt = 0; nt < 8; nt++)
                    MMA16816(acc[mt][nt], a[mt][0],a[mt][1],a[mt][2],a[mt][3],
                             bf[nt>>1][nt&1], bf[nt>>1][2+(nt&1)]);
        }
        if (c + 2 < NC)
            fill_tiles(sb, (c + 2) % 3, Agl, Bgl, lda, ldb, (c+2)*BK, lr, lc);
    }

    int g = lane >> 2, t2 = (lane & 3)*2;
    if (STAGE == 1){
#pragma unroll
        for (int mt = 0; mt < 2; mt++){
            int row = bm + wm*32 + mt*16 + g;
#pragma unroll
            for (int nt = 0; nt < 8; nt++){
                int col = bn + wn*64 + nt*8 + t2;
                *(__nv_bfloat162*)&g_Tb[(size_t)row*NN_ + col] =
                    __floats2bfloat162_rn(acc[mt][nt][0], acc[mt][nt][1]);
                *(__nv_bfloat162*)&g_Tb[(size_t)(row+8)*NN_ + col] =
                    __floats2bfloat162_rn(acc[mt][nt][2], acc[mt][nt][3]);
            }
        }
    } else {
        float bias = W2[2*H_*O_ + o];
        int myv[16]; float lj[16];
#pragma unroll
        for (int nt = 0; nt < 8; nt++){
            int y = bn + wn*64 + nt*8 + t2;
            myv[2*nt]   = mask[b*L_+y];
            myv[2*nt+1] = mask[b*L_+y+1];
            lj[2*nt]    = g_linj[(b*L_+y)*O_+o];
            lj[2*nt+1]  = g_linj[(b*L_+y+1)*O_+o];
        }
#pragma unroll
        for (int mt = 0; mt < 2; mt++)
#pragma unroll
            for (int half = 0; half < 2; half++){
                int x  = bm + wm*32 + mt*16 + g + half*8;
                int mx = mask[b*L_+x];
                float li = g_lini[(b*L_+x)*O_+o] + bias;
                float* orow = out + (size_t)bo*L_*L_ + (size_t)x*L_;
#pragma unroll
                for (int nt = 0; nt < 8; nt++){
                    int y = bn + wn*64 + nt*8 + t2;
                    float v0 = acc[mt][nt][half*2+0] + li + lj[2*nt];
                    float v1 = acc[mt][nt][half*2+1] + li + lj[2*nt+1];
                    if (!mx)         { v0 = -NEGC; v1 = -NEGC; }
                    if (!myv[2*nt])    v0 = -NEGC;
                    if (!myv[2*nt+1])  v1 = -NEGC;
                    if (y   < x)       v0 -= NEGC;
                    if (y+1 < x)       v1 -= NEGC;
                    *(float2*)&orow[y] = make_float2(v0, v1);
                }
            }
    }
}

// ---------------------------------------------------------------------------
extern "C" void kernel_launch(void* const* d_in, const int* in_sizes, int n_in,
                              void* d_out, int out_size) {
    const float* inputs = nullptr;
    const float* w1 = nullptr;
    const float* w2 = nullptr;
    const int*   mask = nullptr;
    for (int i = 0; i < n_in; i++) {
        if      (in_sizes[i] == B_*L_*H_)      inputs = (const float*)d_in[i];
        else if (in_sizes[i] == H_*O_*H_)      w1     = (const float*)d_in[i];
        else if (in_sizes[i] == (2*H_+1)*O_)   w2     = (const float*)d_in[i];
        else if (in_sizes[i] == B_*L_)         mask   = (const int*)d_in[i];
    }
    float* out = (float*)d_out;

    cudaFuncSetAttribute(mma_gemm<1>, cudaFuncAttributeMaxDynamicSharedMemorySize, 3*STG_BYTES);
    cudaFuncSetAttribute(mma_gemm<2>, cudaFuncAttributeMaxDynamicSharedMemorySize, 3*STG_BYTES);

    conv_x<<<(ML_*H_/4)/256, 256>>>(inputs);
    conv_w1<<<dim3(NN_/32, H_/32), dim3(32,8)>>>(w1);
    lin_kernel<<<ML_/8, 256>>>(inputs, w2);
    mma_gemm<1><<<dim3(NN_/BN, ML_/BM), 256, 3*STG_BYTES>>>(w2, mask, out);
    mma_gemm<2><<<dim3(L_/BN, L_/BM, B_*O_), 256, 3*STG_BYTES>>>(w2, mask, out);
}